// round 14
// baseline (speedup 1.0000x reference)
#include <cuda_runtime.h>
#include <cuda_bf16.h>
#include <cstdint>

#define C_    256
#define N_TOK 16384
#define K_CB  8192
#define ZQ_ELEMS 4194304
#define CAP   512
#define MARGIN 4e-4f

// ---------------- scratch ---------------------------------------------------
__device__ float g_zflat[N_TOK * C_];
__device__ float g_e2[K_CB];
__device__ unsigned long long g_min[N_TOK];
__device__ double g_partial[512];
__device__ __nv_bfloat16 g_zbf[N_TOK * C_];
__device__ __nv_bfloat16 g_cbbf[K_CB * C_];
__device__ int g_ccount[N_TOK];
__device__ int g_cand[N_TOK * CAP];

// ---------------- helpers ---------------------------------------------------
__device__ __forceinline__ uint32_t smem_u32(const void* p) {
    uint32_t a;
    asm("{ .reg .u64 t; cvta.to.shared.u64 t, %1; cvt.u32.u64 %0, t; }" : "=r"(a) : "l"(p));
    return a;
}
__device__ __forceinline__ unsigned encf(float f) {
    unsigned u = __float_as_uint(f);
    return (u & 0x80000000u) ? ~u : (u | 0x80000000u);
}
__device__ __forceinline__ float decf(unsigned e) {
    unsigned u = (e & 0x80000000u) ? (e ^ 0x80000000u) : ~e;
    return __uint_as_float(u);
}
#define LDM_X4(r0, r1, r2, r3, a) \
    asm volatile("ldmatrix.sync.aligned.m8n8.x4.shared.b16 {%0,%1,%2,%3}, [%4];" \
                 : "=r"(r0), "=r"(r1), "=r"(r2), "=r"(r3) : "r"(a))
#define MMA16816(c, a, b0, b1) \
    asm volatile("mma.sync.aligned.m16n8k16.row.col.f32.bf16.bf16.f32 " \
                 "{%0,%1,%2,%3}, {%4,%5,%6,%7}, {%8,%9}, {%0,%1,%2,%3};" \
                 : "+f"((c)[0]), "+f"((c)[1]), "+f"((c)[2]), "+f"((c)[3]) \
                 : "r"((a)[0]), "r"((a)[1]), "r"((a)[2]), "r"((a)[3]), "r"(b0), "r"(b1))
#define CP_ASYNC16(dst, src) \
    asm volatile("cp.async.cg.shared.global [%0], [%1], 16;" :: "r"(dst), "l"(src) : "memory")
#define CP_COMMIT() asm volatile("cp.async.commit_group;" ::: "memory")
#define CP_WAIT(n)  asm volatile("cp.async.wait_group %0;" :: "n"(n) : "memory")

// ---------------------------------------------------------------------------
__global__ void k_transpose(const float* __restrict__ z) {
    __shared__ float s[32][33];
    int cb = blockIdx.x, h = blockIdx.y, b = blockIdx.z;
    int tx = threadIdx.x, ty = threadIdx.y;
    s[ty][tx] = z[((b * C_ + cb * 32 + ty) * 32 + h) * 32 + tx];
    __syncthreads();
    float v = s[tx][ty];
    int idx = (b * 1024 + h * 32 + ty) * C_ + cb * 32 + tx;
    g_zflat[idx] = v;
    g_zbf[idx] = __float2bfloat16_rn(v);
}

__global__ void k_e2_init(const float* __restrict__ cbook) {
    int tid = threadIdx.x;
    int gid = blockIdx.x * 256 + tid;
    if (gid < N_TOK) { g_min[gid] = ~0ull; g_ccount[gid] = 0; }
    int k = blockIdx.x * 8 + (tid >> 5), lane = tid & 31;
    float s = 0.f;
#pragma unroll
    for (int j = 0; j < 8; j++) {
        float v = cbook[k * C_ + lane + j * 32];
        g_cbbf[k * C_ + lane + j * 32] = __float2bfloat16_rn(v);
        s += v * v;
    }
    for (int o = 16; o; o >>= 1) s += __shfl_down_sync(0xffffffffu, s, o);
    if (lane == 0) g_e2[k] = s;
}

// ---------------------------------------------------------------------------
// Filter GEMM: per CTA 128 tokens vs 8192 codes, 64 chunks of 128 codes,
// cp.async double-buffered B. 1024 threads: 4x8 warp grid, 32x16 warp tile
// (8 warps/SMSP for latency hiding; per-acc ks order identical to R10/R11).
// ---------------------------------------------------------------------------
#define ASTRIDE 528u
#define OFF_A   0u
#define OFF_B0  67584u
#define OFF_B1  135168u
#define OFF_E2  202752u
#define OFF_RM  203776u
#define SM_TOT  204288u

__global__ __launch_bounds__(1024, 1) void k_gemm() {
    extern __shared__ char smem[];
    uint32_t sb = smem_u32(smem);
    int tid = threadIdx.x, wid = tid >> 5, lane = tid & 31;
    int g = lane >> 2, tg = lane & 3;
    int wm = wid >> 3, wn = wid & 7;          // 4 x 8 warp grid
    int m0 = blockIdx.x * 128;
    float*    e2s = (float*)(smem + OFF_E2);
    unsigned* rm  = (unsigned*)(smem + OFF_RM);

    // A tile (128 x 256 bf16) + B chunk 0 via cp.async, one commit group
    for (int i = tid; i < 4096; i += 1024) {
        int row = i >> 5, c8 = (i & 31) * 8;
        CP_ASYNC16(sb + OFF_A + row * ASTRIDE + c8 * 2, &g_zbf[(m0 + row) * C_ + c8]);
        CP_ASYNC16(sb + OFF_B0 + row * ASTRIDE + c8 * 2, &g_cbbf[row * C_ + c8]);
    }
    CP_COMMIT();
    if (tid < 128) { rm[tid] = 0xFFFFFFFFu; e2s[tid] = g_e2[tid]; }

    // A ldmatrix lane address (m16k16 x4)
    int arow = (lane & 7) + ((lane >> 3) & 1) * 8;
    int akb  = (lane >> 4) & 1;
    uint32_t aBase = sb + OFF_A + (uint32_t)(wm * 32 + arow) * ASTRIDE + (uint32_t)akb * 16;
    // B ldmatrix lane address (n16k16 x4): rows wn*16 + bn8*8 + brow
    int brow = lane & 7;
    int bk   = (lane >> 3) & 1;
    int bn8  = (lane >> 4) & 1;
    uint32_t bBase = sb + (uint32_t)(wn * 16 + bn8 * 8 + brow) * ASTRIDE + (uint32_t)bk * 16;

    for (int chunk = 0; chunk < 64; chunk++) {
        int buf = chunk & 1;
        uint32_t bOff = buf ? OFF_B1 : OFF_B0;
        if (chunk < 63) {
            uint32_t nOff = buf ? OFF_B0 : OFF_B1;
            int n1 = (chunk + 1) * 128;
            for (int i = tid; i < 4096; i += 1024) {
                int row = i >> 5, c8 = (i & 31) * 8;
                CP_ASYNC16(sb + nOff + row * ASTRIDE + c8 * 2, &g_cbbf[(n1 + row) * C_ + c8]);
            }
            if (tid < 128) e2s[(buf ^ 1) * 128 + tid] = g_e2[n1 + tid];
            CP_COMMIT();
            CP_WAIT(1);
        } else {
            CP_WAIT(0);
        }
        __syncthreads();

        float acc[2][2][4];
#pragma unroll
        for (int mt = 0; mt < 2; mt++)
#pragma unroll
            for (int nt = 0; nt < 2; nt++)
#pragma unroll
                for (int c = 0; c < 4; c++) acc[mt][nt][c] = 0.f;

#pragma unroll
        for (int ks = 0; ks < 16; ks++) {
            uint32_t a[2][4];
#pragma unroll
            for (int mt = 0; mt < 2; mt++)
                LDM_X4(a[mt][0], a[mt][1], a[mt][2], a[mt][3],
                       aBase + (uint32_t)(mt * 16) * ASTRIDE + (uint32_t)ks * 32);
            uint32_t b[4];
            LDM_X4(b[0], b[1], b[2], b[3], bBase + bOff + (uint32_t)ks * 32);
#pragma unroll
            for (int mt = 0; mt < 2; mt++) {
                MMA16816(acc[mt][0], a[mt], b[0], b[1]);
                MMA16816(acc[mt][1], a[mt], b[2], b[3]);
            }
        }

        // epilogue: m = fma(-2, acc, e2) in place
#pragma unroll
        for (int mt = 0; mt < 2; mt++)
#pragma unroll
            for (int nt = 0; nt < 2; nt++) {
                int nl = buf * 128 + wn * 16 + nt * 8 + tg * 2;
                float e0 = e2s[nl], e1 = e2s[nl + 1];
                acc[mt][nt][0] = __fmaf_rn(-2.f, acc[mt][nt][0], e0);
                acc[mt][nt][1] = __fmaf_rn(-2.f, acc[mt][nt][1], e1);
                acc[mt][nt][2] = __fmaf_rn(-2.f, acc[mt][nt][2], e0);
                acc[mt][nt][3] = __fmaf_rn(-2.f, acc[mt][nt][3], e1);
            }

        // pass 1: per-token chunk minima -> rm (monotone atomicMin)
#pragma unroll
        for (int mt = 0; mt < 2; mt++) {
            unsigned e0 = 0xFFFFFFFFu, e1 = 0xFFFFFFFFu;
#pragma unroll
            for (int nt = 0; nt < 2; nt++) {
                e0 = min(e0, min(encf(acc[mt][nt][0]), encf(acc[mt][nt][1])));
                e1 = min(e1, min(encf(acc[mt][nt][2]), encf(acc[mt][nt][3])));
            }
            e0 = min(e0, __shfl_xor_sync(0xffffffffu, e0, 1));
            e0 = min(e0, __shfl_xor_sync(0xffffffffu, e0, 2));
            e1 = min(e1, __shfl_xor_sync(0xffffffffu, e1, 1));
            e1 = min(e1, __shfl_xor_sync(0xffffffffu, e1, 2));
            if (tg == 0) {
                atomicMin(&rm[wm * 32 + mt * 16 + g], e0);
                atomicMin(&rm[wm * 32 + mt * 16 + 8 + g], e1);
            }
        }
        if (chunk == 0) __syncthreads();   // cold-start threshold visibility

        // pass 2: emit candidates within MARGIN of token min-so-far
#pragma unroll
        for (int mt = 0; mt < 2; mt++) {
            int r0 = wm * 32 + mt * 16 + g, r1 = r0 + 8;
            float th0 = decf(rm[r0]) + MARGIN;
            float th1 = decf(rm[r1]) + MARGIN;
            int tok0 = m0 + r0, tok1 = m0 + r1;
#pragma unroll
            for (int nt = 0; nt < 2; nt++) {
                int code = chunk * 128 + wn * 16 + nt * 8 + tg * 2;
                if (acc[mt][nt][0] < th0) { int s = atomicAdd(&g_ccount[tok0], 1); if (s < CAP) g_cand[tok0 * CAP + s] = code; }
                if (acc[mt][nt][1] < th0) { int s = atomicAdd(&g_ccount[tok0], 1); if (s < CAP) g_cand[tok0 * CAP + s] = code + 1; }
                if (acc[mt][nt][2] < th1) { int s = atomicAdd(&g_ccount[tok1], 1); if (s < CAP) g_cand[tok1 * CAP + s] = code; }
                if (acc[mt][nt][3] < th1) { int s = atomicAdd(&g_ccount[tok1], 1); if (s < CAP) g_cand[tok1 * CAP + s] = code + 1; }
            }
        }
        __syncthreads();   // protects B buffer reuse + e2s halves across chunks
    }
}

// ---------------------------------------------------------------------------
// Exact rescue: block per token, warp per candidate (fp32, R2 numerics)
// ---------------------------------------------------------------------------
__global__ __launch_bounds__(256, 4) void k_exact(const float* __restrict__ cbook) {
    __shared__ float zrow[256];
    int tok = blockIdx.x;
    int tid = threadIdx.x, wid = tid >> 5, lane = tid & 31;
    zrow[tid] = g_zflat[tok * C_ + tid];
    int cnt = g_ccount[tok]; if (cnt > CAP) cnt = CAP;
    __syncthreads();
    float z2 = 0.f;
#pragma unroll
    for (int j = 0; j < 8; j++) { float v = zrow[lane + 32 * j]; z2 += v * v; }
    for (int o = 16; o; o >>= 1) z2 += __shfl_down_sync(0xffffffffu, z2, o);
    for (int slot = wid; slot < cnt; slot += 8) {
        int code = g_cand[tok * CAP + slot];
        float s = 0.f;
#pragma unroll
        for (int j = 0; j < 8; j++)
            s += zrow[lane + 32 * j] * cbook[code * C_ + lane + 32 * j];
        for (int o = 16; o; o >>= 1) s += __shfl_down_sync(0xffffffffu, s, o);
        if (lane == 0) {
            float sz = __fadd_rn(z2, g_e2[code]);
            float d = __fadd_rn(sz, -2.0f * s);
            unsigned long long p = ((unsigned long long)__float_as_uint(d) << 32) | (unsigned)code;
            atomicMin(&g_min[tok], p);
        }
    }
}

// ---------------------------------------------------------------------------
__global__ void k_output(const float* __restrict__ cbook, float* __restrict__ out) {
    __shared__ float srow[256];
    __shared__ double sred[256];
    int t = threadIdx.x, bw = blockIdx.x;
    int b = bw >> 5, w = bw & 31;
    int gam = t & 7, h = t >> 3;
    double local = 0.0;
    for (int q = 0; q < 32; q++) {
        int np = b * 1024 + w * 32 + q;
        unsigned idx = (unsigned)(g_min[np] & 0xffffffffu);
        __syncthreads();
        srow[t] = cbook[idx * C_ + t];
        __syncthreads();
        int c = q * 8 + gam, cc = (gam << 5) | h;
        float zq = srow[cc];
        float zp = g_zflat[(b * 1024 + h * 32 + w) * C_ + c];
        out[((b * 32 + h) * 32 + w) * C_ + c] = zq;
        float df = zp - zq;
        local += (double)df * (double)df;
    }
    sred[t] = local;
    __syncthreads();
    for (int o = 128; o; o >>= 1) { if (t < o) sred[t] += sred[t + o]; __syncthreads(); }
    if (t == 0) g_partial[bw] = sred[0];
}

__global__ void k_final(float* __restrict__ out, int has_loss, int has_idx) {
    __shared__ double sr[256];
    int t = threadIdx.x, gid = blockIdx.x * 256 + t;
    if (has_idx && gid < N_TOK)
        out[ZQ_ELEMS + 1 + gid] = (float)(unsigned)(g_min[gid] & 0xffffffffu);
    if (has_loss && blockIdx.x == 0) {
        sr[t] = g_partial[t] + g_partial[t + 256];
        __syncthreads();
        for (int o = 128; o; o >>= 1) { if (t < o) sr[t] += sr[t + o]; __syncthreads(); }
        if (t == 0) out[ZQ_ELEMS] = (float)(1.25 * sr[0] / (double)ZQ_ELEMS);
    }
}

// ---------------------------------------------------------------------------
extern "C" void kernel_launch(void* const* d_in, const int* in_sizes, int n_in,
                              void* d_out, int out_size) {
    const float* z  = (const float*)d_in[0];
    const float* cb = (const float*)d_in[1];
    float* out = (float*)d_out;

    cudaFuncSetAttribute(k_gemm, cudaFuncAttributeMaxDynamicSharedMemorySize, SM_TOT);

    k_transpose<<<dim3(8, 32, 16), dim3(32, 32)>>>(z);
    k_e2_init<<<1024, 256>>>(cb);
    k_gemm<<<128, 1024, SM_TOT>>>();
    k_exact<<<N_TOK, 256>>>(cb);
    if (out_size >= ZQ_ELEMS) k_output<<<512, 256>>>(cb, out);
    int has_loss = (out_size >= ZQ_ELEMS + 1) ? 1 : 0;
    int has_idx  = (out_size >= ZQ_ELEMS + 1 + N_TOK) ? 1 : 0;
    k_final<<<64, 256>>>(out, has_loss, has_idx);
}